// round 8
// baseline (speedup 1.0000x reference)
#include <cuda_runtime.h>
#include <cuda_bf16.h>
#include <math.h>
#include <stdint.h>

typedef unsigned long long ull;

#define NE 80000
#define TT 2000
#define SS 12
#define HH 128
#define EB 64                      // electrons per CTA (MMA M)
#define MASK_COEF 1.2615662610f    // GAUSS_NORM / sqrt(0.1)

// smem word offsets (A rows / Bt rows padded to 68 words; 4n mod 32 bank spread)
#define SW_AHI 0                   // 64 x 68
#define SW_ALO (SW_AHI + EB*68)    // 4352
#define SW_BHI (SW_ALO + EB*68)    // 8704: Bt[n=128][kp=64] stride 68
#define SW_BLO (SW_BHI + 128*68)   // 17408
#define SW_W3  (SW_BLO + 128*68)   // 26112: 128*12
#define SW_B2  (SW_W3 + HH*SS)     // 27648
#define SW_B3  (SW_B2 + HH)        // 27776 (+16 pad)
#define SW_TOT (SW_B3 + 16)        // 27792 words = 111168 B
#define SW_H2  0                   // h2[64][130] f32 reuses A region (8320 <= 8704)
#define H2_STRIDE 130

__device__ __forceinline__ ull fma2(ull a, ull b, ull c) {
    ull d; asm("fma.rn.f32x2 %0, %1, %2, %3;" : "=l"(d) : "l"(a), "l"(b), "l"(c)); return d;
}
__device__ __forceinline__ ull pack2(float lo, float hi) {
    ull d; asm("mov.b64 %0, {%1, %2};" : "=l"(d) : "f"(lo), "f"(hi)); return d;
}
__device__ __forceinline__ float2 unpack2(ull v) {
    float2 r; asm("mov.b64 {%0, %1}, %2;" : "=f"(r.x), "=f"(r.y) : "l"(v)); return r;
}
__device__ __forceinline__ uint32_t bfpack(float a, float b) {
    __nv_bfloat162 t(__float2bfloat16(a), __float2bfloat16(b));
    return *(uint32_t*)&t;
}
__device__ __forceinline__ uint32_t smem_u32(const void* p) {
    uint32_t a;
    asm("{ .reg .u64 t; cvta.to.shared.u64 t, %1; cvt.u32.u64 %0, t; }" : "=r"(a) : "l"(p));
    return a;
}
__device__ __forceinline__ void ldsm4(uint32_t* r, uint32_t addr) {
    asm volatile("ldmatrix.sync.aligned.m8n8.x4.shared.b16 {%0,%1,%2,%3}, [%4];"
        : "=r"(r[0]), "=r"(r[1]), "=r"(r[2]), "=r"(r[3]) : "r"(addr));
}
__device__ __forceinline__ void mma16816(float* c, const uint32_t* a, uint32_t b0, uint32_t b1) {
    asm volatile(
        "mma.sync.aligned.m16n8k16.row.col.f32.bf16.bf16.f32 "
        "{%0,%1,%2,%3}, {%4,%5,%6,%7}, {%8,%9}, {%0,%1,%2,%3};"
        : "+f"(c[0]), "+f"(c[1]), "+f"(c[2]), "+f"(c[3])
        : "r"(a[0]), "r"(a[1]), "r"(a[2]), "r"(a[3]), "r"(b0), "r"(b1));
}

__global__ void zero_kernel(float* __restrict__ out, int n) {
    int i = blockIdx.x * blockDim.x + threadIdx.x;
    if (i < n) out[i] = 0.0f;
}

__global__ __launch_bounds__(256, 2)
void fused_sensor_kernel(
    const float* __restrict__ de,    // (B,N,3)
    const float* __restrict__ mask,  // (B,N)
    const float* __restrict__ W1,    // (3,H)
    const float* __restrict__ b1,    // (H)
    const float* __restrict__ W2,    // (H,H)
    const float* __restrict__ b2,    // (H)
    const float* __restrict__ W3,    // (H,S)
    const float* __restrict__ b3,    // (S)
    float* __restrict__ out)         // (B,S,T)
{
    extern __shared__ uint32_t smw[];
    float* smf = (float*)smw;
    const uint32_t smb = smem_u32(smw);
    const int tid  = threadIdx.x;
    const int lane = tid & 31;
    const int wid  = tid >> 5;

    // ---------- stage Bt[n][kp] = bf16x2(W2[2kp][n], W2[2kp+1][n]), split hi/lo ----------
#pragma unroll 4
    for (int i = 0; i < 32; ++i) {
        int idx = tid + i * 256;               // 8192 entries
        int kp = idx >> 7, n = idx & 127;
        float v0 = W2[(2 * kp) * HH + n];      // coalesced
        float v1 = W2[(2 * kp + 1) * HH + n];
        float h0 = __bfloat162float(__float2bfloat16(v0));
        float h1 = __bfloat162float(__float2bfloat16(v1));
        smw[SW_BHI + n * 68 + kp] = bfpack(v0, v1);
        smw[SW_BLO + n * 68 + kp] = bfpack(v0 - h0, v1 - h1);
    }
    // small weights to smem
    for (int i = tid; i < HH * SS; i += 256) smf[SW_W3 + i] = W3[i];
    if (tid < HH) smf[SW_B2 + tid] = b2[tid];
    if (tid < SS) smf[SW_B3 + tid] = b3[tid];

    // ---------- layer 1 -> Apack (4 threads per electron, 16 k-pairs each) ----------
    const int el = tid >> 2;                   // local electron 0..63
    const int q  = tid & 3;
    const int eg = blockIdx.x * EB + el;
    const float x0 = de[3 * eg + 0];
    const float x1 = de[3 * eg + 1];
    const float x2 = de[3 * eg + 2];
    const float msk = mask[eg];
#pragma unroll 4
    for (int i = 0; i < 16; ++i) {
        int kp = q * 16 + i, k = 2 * kp;
        float v0 = fmaf(x2, W1[2 * HH + k],     fmaf(x1, W1[HH + k],     fmaf(x0, W1[k],     b1[k])));
        float v1 = fmaf(x2, W1[2 * HH + k + 1], fmaf(x1, W1[HH + k + 1], fmaf(x0, W1[k + 1], b1[k + 1])));
        v0 = fmaxf(v0, 0.0f);
        v1 = fmaxf(v1, 0.0f);
        float h0 = __bfloat162float(__float2bfloat16(v0));
        float h1 = __bfloat162float(__float2bfloat16(v1));
        smw[SW_AHI + el * 68 + kp] = bfpack(v0, v1);
        smw[SW_ALO + el * 68 + kp] = bfpack(v0 - h0, v1 - h1);
    }
    __syncthreads();

    // ---------- layer-2 GEMM: warp (mw,nw) owns 32 rows x 32 cols; ldmatrix frags ----------
    const int mw = wid & 1, nw = wid >> 1;
    const int m0 = mw * 32, n0 = nw * 32;
    float acc[2][4][4];
#pragma unroll
    for (int mt = 0; mt < 2; ++mt)
#pragma unroll
        for (int nt = 0; nt < 4; ++nt)
#pragma unroll
            for (int c = 0; c < 4; ++c) acc[mt][nt][c] = 0.0f;

    // A tiles: t0 rows+0..7 @kb, t1 rows+8..15 @kb, t2 rows @kb+4, t3 rows+8 @kb+4
    const uint32_t aoff = ((m0 + (lane & 7) + ((lane >> 3) & 1) * 8) * 68 + (lane >> 4) * 4) * 4;
    // B tiles: t0 n+0..7 @kb, t1 n+0..7 @kb+4, t2 n+8..15 @kb, t3 n+8..15 @kb+4
    const uint32_t boff = ((n0 + (lane & 7) + (lane >> 4) * 8) * 68 + ((lane >> 3) & 1) * 4) * 4;

#pragma unroll 1
    for (int sp = 0; sp < 3; ++sp) {
        const uint32_t Ab = smb + (sp == 1 ? SW_ALO : SW_AHI) * 4 + aoff;
        const uint32_t Bb = smb + (sp == 2 ? SW_BLO : SW_BHI) * 4 + boff;
#pragma unroll
        for (int kk = 0; kk < 8; ++kk) {
            uint32_t af[2][4], bf[2][4];
            ldsm4(af[0], Ab + kk * 32);
            ldsm4(af[1], Ab + 16 * 68 * 4 + kk * 32);
            ldsm4(bf[0], Bb + kk * 32);
            ldsm4(bf[1], Bb + 16 * 68 * 4 + kk * 32);
#pragma unroll
            for (int mt = 0; mt < 2; ++mt)
#pragma unroll
                for (int g = 0; g < 2; ++g) {
                    mma16816(acc[mt][2 * g],     af[mt], bf[g][0], bf[g][1]);
                    mma16816(acc[mt][2 * g + 1], af[mt], bf[g][2], bf[g][3]);
                }
        }
    }
    __syncthreads();   // GEMM reads of A region done before h2 overwrites it

    // ---------- epilogue: h2 = relu(D + b2) -> smem ----------
    {
        const int r = lane >> 2, c2 = lane & 3;
#pragma unroll
        for (int mt = 0; mt < 2; ++mt)
#pragma unroll
            for (int nt = 0; nt < 4; ++nt) {
                int j = n0 + nt * 8 + 2 * c2;
                float bj0 = smf[SW_B2 + j], bj1 = smf[SW_B2 + j + 1];
                int row0 = m0 + mt * 16 + r;
                float2 v0 = make_float2(fmaxf(acc[mt][nt][0] + bj0, 0.0f),
                                        fmaxf(acc[mt][nt][1] + bj1, 0.0f));
                float2 v1 = make_float2(fmaxf(acc[mt][nt][2] + bj0, 0.0f),
                                        fmaxf(acc[mt][nt][3] + bj1, 0.0f));
                *(float2*)&smf[SW_H2 + row0 * H2_STRIDE + j] = v0;
                *(float2*)&smf[SW_H2 + (row0 + 8) * H2_STRIDE + j] = v1;
            }
    }
    __syncthreads();

    // ---------- layer 3 (f32x2) : thread handles j in [32q, 32q+32) ----------
    ull accS[6];
#pragma unroll
    for (int sp = 0; sp < 6; ++sp) accS[sp] = 0ULL;
    const float* h2row = &smf[SW_H2 + el * H2_STRIDE + q * 32];
#pragma unroll 8
    for (int jj = 0; jj < 32; ++jj) {
        float h2 = h2row[jj];
        ull hd = pack2(h2, h2);
        const ull* w3r = (const ull*)&smf[SW_W3 + (q * 32 + jj) * SS];
#pragma unroll
        for (int sp = 0; sp < 6; ++sp) accS[sp] = fma2(hd, w3r[sp], accS[sp]);
    }
    float resp[SS];
#pragma unroll
    for (int sp = 0; sp < 6; ++sp) {
        float2 v = unpack2(accS[sp]);
        v.x += __shfl_xor_sync(0xffffffffu, v.x, 1);
        v.x += __shfl_xor_sync(0xffffffffu, v.x, 2);
        v.y += __shfl_xor_sync(0xffffffffu, v.y, 1);
        v.y += __shfl_xor_sync(0xffffffffu, v.y, 2);
        resp[2 * sp]     = v.x + smf[SW_B3 + 2 * sp];
        resp[2 * sp + 1] = v.y + smf[SW_B3 + 2 * sp + 1];
    }

    // ---------- sparse Gaussian scatter (exp(-5d^2) < 3e-20 beyond |d|=3) ----------
    {
        const float z = x2;
        const float c = msk * MASK_COEF;
        int t0 = (int)ceilf(z - 3.0f);
        int t1 = (int)floorf(z + 3.0f);
        if (t0 < 0) t0 = 0;
        if (t1 > TT - 1) t1 = TT - 1;
        const int b = eg / 10000;
        float* ob = out + (size_t)b * SS * TT;
        for (int t = t0 + q; t <= t1; t += 4) {     // ticks split across 4 threads
            float d = (float)t - z;
            float w = __expf(-5.0f * d * d) * c;
#pragma unroll
            for (int s = 0; s < SS; ++s)
                atomicAdd(&ob[s * TT + t], w * resp[s]);
        }
    }
}

extern "C" void kernel_launch(void* const* d_in, const int* in_sizes, int n_in,
                              void* d_out, int out_size) {
    const float* de   = (const float*)d_in[0];
    const float* mask = (const float*)d_in[1];
    const float* W1   = (const float*)d_in[2];
    const float* b1   = (const float*)d_in[3];
    const float* W2   = (const float*)d_in[4];
    const float* b2   = (const float*)d_in[5];
    const float* W3   = (const float*)d_in[6];
    const float* b3   = (const float*)d_in[7];
    float* out = (float*)d_out;

    const int total_out = 8 * SS * TT;  // 192000
    zero_kernel<<<(total_out + 255) / 256, 256>>>(out, total_out);

    const int smem_bytes = SW_TOT * 4;  // 111168
    cudaFuncSetAttribute(fused_sensor_kernel,
                         cudaFuncAttributeMaxDynamicSharedMemorySize, smem_bytes);

    fused_sensor_kernel<<<NE / EB, 256, smem_bytes>>>(   // 1250 CTAs
        de, mask, W1, b1, W2, b2, W3, b3, out);
}

// round 10
// speedup vs baseline: 2.0018x; 2.0018x over previous
#include <cuda_runtime.h>
#include <cuda_bf16.h>
#include <math.h>
#include <stdint.h>

typedef unsigned long long ull;

#define NE 80000
#define TT 2000
#define SS 12
#define HH 128
#define EB 64                      // electrons per CTA (MMA M)
#define MASK_COEF 1.2615662610f    // GAUSS_NORM / sqrt(0.1)

// smem word offsets
#define SW_AHI 0                   // 64 x 68 (bf16x2 k-pairs, padded stride)
#define SW_ALO (SW_AHI + EB*68)    // 4352
#define SW_W3  (SW_ALO + EB*68)    // 8704
#define SW_B2  (SW_W3 + HH*SS)     // 10240
#define SW_B3  (SW_B2 + HH)        // 10368
#define SW_TOT (SW_B3 + 16)        // 10384 words = 41536 B
#define SW_H2  0                   // h2[64][130] reuses A region (8320 <= 8704)
#define H2_STRIDE 130

// B fragments pre-packed: [spB(2)][kk(8)][ntile(16)][lane(32)] -> (b0,b1)
__device__ ull g_Bfrag[2 * 8 * 16 * 32];

__device__ __forceinline__ ull fma2(ull a, ull b, ull c) {
    ull d; asm("fma.rn.f32x2 %0, %1, %2, %3;" : "=l"(d) : "l"(a), "l"(b), "l"(c)); return d;
}
__device__ __forceinline__ ull pack2(float lo, float hi) {
    ull d; asm("mov.b64 %0, {%1, %2};" : "=l"(d) : "f"(lo), "f"(hi)); return d;
}
__device__ __forceinline__ float2 unpack2(ull v) {
    float2 r; asm("mov.b64 {%0, %1}, %2;" : "=f"(r.x), "=f"(r.y) : "l"(v)); return r;
}
__device__ __forceinline__ uint32_t bfpack(float a, float b) {
    __nv_bfloat162 t(__float2bfloat16(a), __float2bfloat16(b));
    return *(uint32_t*)&t;
}
__device__ __forceinline__ uint32_t smem_u32(const void* p) {
    uint32_t a;
    asm("{ .reg .u64 t; cvta.to.shared.u64 t, %1; cvt.u32.u64 %0, t; }" : "=r"(a) : "l"(p));
    return a;
}
__device__ __forceinline__ void ldsm4(uint32_t* r, uint32_t addr) {
    asm volatile("ldmatrix.sync.aligned.m8n8.x4.shared.b16 {%0,%1,%2,%3}, [%4];"
        : "=r"(r[0]), "=r"(r[1]), "=r"(r[2]), "=r"(r[3]) : "r"(addr));
}
__device__ __forceinline__ void mma16816(float* c, const uint32_t* a, uint32_t b0, uint32_t b1) {
    asm volatile(
        "mma.sync.aligned.m16n8k16.row.col.f32.bf16.bf16.f32 "
        "{%0,%1,%2,%3}, {%4,%5,%6,%7}, {%8,%9}, {%0,%1,%2,%3};"
        : "+f"(c[0]), "+f"(c[1]), "+f"(c[2]), "+f"(c[3])
        : "r"(a[0]), "r"(a[1]), "r"(a[2]), "r"(a[3]), "r"(b0), "r"(b1));
}

__global__ void zero_kernel(float* __restrict__ out, int n) {
    int i = blockIdx.x * blockDim.x + threadIdx.x;
    if (i < n) out[i] = 0.0f;
}

// one-shot W2 -> split-bf16 fragment layout
__global__ void prep_kernel(const float* __restrict__ W2) {
    int idx = blockIdx.x * 256 + threadIdx.x;   // 8192 entries
    int lane  = idx & 31;
    int ntile = (idx >> 5) & 15;
    int kk    = (idx >> 9) & 7;
    int spB   = idx >> 12;
    int kp0 = kk * 8 + (lane & 3);              // b0 k-pair
    int n   = ntile * 8 + (lane >> 2);
    float v0 = W2[(2 * kp0) * HH + n];
    float v1 = W2[(2 * kp0 + 1) * HH + n];
    float w0 = W2[(2 * (kp0 + 4)) * HH + n];    // b1 k-pair (+8 in k)
    float w1 = W2[(2 * (kp0 + 4) + 1) * HH + n];
    uint32_t b0, b1;
    if (spB == 0) {
        b0 = bfpack(v0, v1);
        b1 = bfpack(w0, w1);
    } else {
        b0 = bfpack(v0 - __bfloat162float(__float2bfloat16(v0)),
                    v1 - __bfloat162float(__float2bfloat16(v1)));
        b1 = bfpack(w0 - __bfloat162float(__float2bfloat16(w0)),
                    w1 - __bfloat162float(__float2bfloat16(w1)));
    }
    g_Bfrag[idx] = ((ull)b1 << 32) | (ull)b0;
}

__global__ __launch_bounds__(128, 4)
void fused_sensor_kernel(
    const float* __restrict__ de,    // (B,N,3)
    const float* __restrict__ mask,  // (B,N)
    const float* __restrict__ W1,    // (3,H)
    const float* __restrict__ b1,    // (H)
    const float* __restrict__ b2,    // (H)
    const float* __restrict__ W3,    // (H,S)
    const float* __restrict__ b3,    // (S)
    float* __restrict__ out)         // (B,S,T)
{
    extern __shared__ uint32_t smw[];
    float* smf = (float*)smw;
    const uint32_t smb = smem_u32(smw);
    const int tid  = threadIdx.x;
    const int lane = tid & 31;
    const int wid  = tid >> 5;

    // ---- small weights to smem ----
    for (int i = tid; i < HH * SS; i += 128) smf[SW_W3 + i] = W3[i];
    if (tid < HH) smf[SW_B2 + tid] = b2[tid];
    if (tid < SS) smf[SW_B3 + tid] = b3[tid];

    // ---- layer 1 -> A hi/lo (2 threads per electron, 32 k-pairs each) ----
    const int el = tid >> 1;
    const int q  = tid & 1;
    const int eg = blockIdx.x * EB + el;
    const float x0 = de[3 * eg + 0];
    const float x1 = de[3 * eg + 1];
    const float x2 = de[3 * eg + 2];
    const float msk = mask[eg];
#pragma unroll 4
    for (int i = 0; i < 32; ++i) {
        int kp = q * 32 + i, k = 2 * kp;
        float v0 = fmaf(x2, W1[2 * HH + k],     fmaf(x1, W1[HH + k],     fmaf(x0, W1[k],     b1[k])));
        float v1 = fmaf(x2, W1[2 * HH + k + 1], fmaf(x1, W1[HH + k + 1], fmaf(x0, W1[k + 1], b1[k + 1])));
        v0 = fmaxf(v0, 0.0f);
        v1 = fmaxf(v1, 0.0f);
        float h0 = __bfloat162float(__float2bfloat16(v0));
        float h1 = __bfloat162float(__float2bfloat16(v1));
        smw[SW_AHI + el * 68 + kp] = bfpack(v0, v1);
        smw[SW_ALO + el * 68 + kp] = bfpack(v0 - h0, v1 - h1);
    }
    __syncthreads();

    // ---- layer-2 GEMM: 4 warps, warp (mw,nw) owns 32 rows x 64 cols ----
    const int mw = wid & 1, nw = wid >> 1;
    const int m0 = mw * 32;
    float acc[2][8][4];
#pragma unroll
    for (int mt = 0; mt < 2; ++mt)
#pragma unroll
        for (int nt = 0; nt < 8; ++nt)
#pragma unroll
            for (int c = 0; c < 4; ++c) acc[mt][nt][c] = 0.0f;

    const uint32_t aoff = ((m0 + (lane & 7) + ((lane >> 3) & 1) * 8) * 68 + (lane >> 4) * 4) * 4;

#pragma unroll 1
    for (int sp = 0; sp < 3; ++sp) {
        const uint32_t Ab = smb + (sp == 1 ? SW_ALO : SW_AHI) * 4 + aoff;
        const ull* Bp = g_Bfrag + (sp == 2 ? 4096 : 0) + nw * 8 * 32 + lane;
#pragma unroll
        for (int kk = 0; kk < 8; ++kk) {
            uint32_t af[2][4];
            ldsm4(af[0], Ab + kk * 32);
            ldsm4(af[1], Ab + 16 * 68 * 4 + kk * 32);
            const ull* Bk = Bp + kk * 512;
            ull bfr[8];
#pragma unroll
            for (int nt = 0; nt < 8; ++nt) bfr[nt] = Bk[nt * 32];   // LDG.64, L1-hot
#pragma unroll
            for (int mt = 0; mt < 2; ++mt)
#pragma unroll
                for (int nt = 0; nt < 8; ++nt)
                    mma16816(acc[mt][nt], af[mt],
                             (uint32_t)bfr[nt], (uint32_t)(bfr[nt] >> 32));
        }
    }
    __syncthreads();   // GEMM reads of A region done before h2 overwrites it

    // ---- epilogue: h2 = relu(D + b2) -> smem ----
    {
        const int r = lane >> 2, c2 = lane & 3;
#pragma unroll
        for (int mt = 0; mt < 2; ++mt)
#pragma unroll
            for (int nt = 0; nt < 8; ++nt) {
                int j = nw * 64 + nt * 8 + 2 * c2;
                float bj0 = smf[SW_B2 + j], bj1 = smf[SW_B2 + j + 1];
                int row0 = m0 + mt * 16 + r;
                float2 v0 = make_float2(fmaxf(acc[mt][nt][0] + bj0, 0.0f),
                                        fmaxf(acc[mt][nt][1] + bj1, 0.0f));
                float2 v1 = make_float2(fmaxf(acc[mt][nt][2] + bj0, 0.0f),
                                        fmaxf(acc[mt][nt][3] + bj1, 0.0f));
                *(float2*)&smf[SW_H2 + row0 * H2_STRIDE + j] = v0;
                *(float2*)&smf[SW_H2 + (row0 + 8) * H2_STRIDE + j] = v1;
            }
    }
    __syncthreads();

    // ---- layer 3 (f32x2): thread handles j in [64q, 64q+64) ----
    ull accS[6];
#pragma unroll
    for (int sp = 0; sp < 6; ++sp) accS[sp] = 0ULL;
    const float* h2row = &smf[SW_H2 + el * H2_STRIDE + q * 64];
#pragma unroll 8
    for (int jj = 0; jj < 64; ++jj) {
        float h2 = h2row[jj];
        ull hd = pack2(h2, h2);
        const ull* w3r = (const ull*)&smf[SW_W3 + (q * 64 + jj) * SS];
#pragma unroll
        for (int sp = 0; sp < 6; ++sp) accS[sp] = fma2(hd, w3r[sp], accS[sp]);
    }
    float resp[SS];
#pragma unroll
    for (int sp = 0; sp < 6; ++sp) {
        float2 v = unpack2(accS[sp]);
        v.x += __shfl_xor_sync(0xffffffffu, v.x, 1);
        v.y += __shfl_xor_sync(0xffffffffu, v.y, 1);
        resp[2 * sp]     = v.x + smf[SW_B3 + 2 * sp];
        resp[2 * sp + 1] = v.y + smf[SW_B3 + 2 * sp + 1];
    }

    // ---- sparse Gaussian scatter (exp(-5d^2) < 3e-20 beyond |d|=3) ----
    {
        const float z = x2;
        const float c = msk * MASK_COEF;
        int t0 = (int)ceilf(z - 3.0f);
        int t1 = (int)floorf(z + 3.0f);
        if (t0 < 0) t0 = 0;
        if (t1 > TT - 1) t1 = TT - 1;
        const int b = eg / 10000;
        float* ob = out + (size_t)b * SS * TT;
        for (int t = t0 + q; t <= t1; t += 2) {
            float d = (float)t - z;
            float w = __expf(-5.0f * d * d) * c;
#pragma unroll
            for (int s = 0; s < SS; ++s)
                atomicAdd(&ob[s * TT + t], w * resp[s]);
        }
    }
}

extern "C" void kernel_launch(void* const* d_in, const int* in_sizes, int n_in,
                              void* d_out, int out_size) {
    const float* de   = (const float*)d_in[0];
    const float* mask = (const float*)d_in[1];
    const float* W1   = (const float*)d_in[2];
    const float* b1   = (const float*)d_in[3];
    const float* W2   = (const float*)d_in[4];
    const float* b2   = (const float*)d_in[5];
    const float* W3   = (const float*)d_in[6];
    const float* b3   = (const float*)d_in[7];
    float* out = (float*)d_out;

    const int total_out = 8 * SS * TT;  // 192000
    zero_kernel<<<(total_out + 255) / 256, 256>>>(out, total_out);
    prep_kernel<<<32, 256>>>(W2);       // 8192 fragment entries

    const int smem_bytes = SW_TOT * 4;  // 41536
    cudaFuncSetAttribute(fused_sensor_kernel,
                         cudaFuncAttributeMaxDynamicSharedMemorySize, smem_bytes);

    fused_sensor_kernel<<<NE / EB, 128, smem_bytes>>>(   // 1250 CTAs
        de, mask, W1, b1, b2, W3, b3, out);
}

// round 12
// speedup vs baseline: 2.6441x; 1.3208x over previous
#include <cuda_runtime.h>
#include <cuda_bf16.h>
#include <math.h>
#include <stdint.h>

typedef unsigned long long ull;

#define NE 80000
#define TT 2000
#define SS 12
#define HH 128
#define EB 64                      // electrons per CTA (MMA M)
#define MASK_COEF 1.2615662610f    // GAUSS_NORM / sqrt(0.1)

// smem word offsets
#define SW_AHI 0                   // 64 x 68 (bf16x2 k-pairs, padded stride); reused for h2-hi
#define SW_ALO (SW_AHI + EB*68)    // 4352; reused for h2-lo
#define SW_B2  (SW_ALO + EB*68)    // 8704
#define SW_B3  (SW_B2 + HH)        // 8832 (+16)
#define SW_RESP (SW_B3 + 16)       // 8848: 64 x 12 f32
#define SW_TOT (SW_RESP + EB*SS)   // 9616 words = 38464 B

// W2 fragments: [spB(2)][kk(8)][ntile(16)][lane(32)] -> (b0,b1)
__device__ ull g_Bfrag[2 * 8 * 16 * 32];
// W3 fragments: [spB(2)][kk(8)][ntile(2)][lane(32)]  (N=16: sensors 0..11 + zero pad)
__device__ ull g_W3frag[2 * 8 * 2 * 32];

__device__ __forceinline__ ull pack2(float lo, float hi) {
    ull d; asm("mov.b64 %0, {%1, %2};" : "=l"(d) : "f"(lo), "f"(hi)); return d;
}
__device__ __forceinline__ uint32_t bfpack(float a, float b) {
    __nv_bfloat162 t(__float2bfloat16(a), __float2bfloat16(b));
    return *(uint32_t*)&t;
}
__device__ __forceinline__ uint32_t smem_u32(const void* p) {
    uint32_t a;
    asm("{ .reg .u64 t; cvta.to.shared.u64 t, %1; cvt.u32.u64 %0, t; }" : "=r"(a) : "l"(p));
    return a;
}
__device__ __forceinline__ void ldsm4(uint32_t* r, uint32_t addr) {
    asm volatile("ldmatrix.sync.aligned.m8n8.x4.shared.b16 {%0,%1,%2,%3}, [%4];"
        : "=r"(r[0]), "=r"(r[1]), "=r"(r[2]), "=r"(r[3]) : "r"(addr));
}
__device__ __forceinline__ void mma16816(float* c, const uint32_t* a, uint32_t b0, uint32_t b1) {
    asm volatile(
        "mma.sync.aligned.m16n8k16.row.col.f32.bf16.bf16.f32 "
        "{%0,%1,%2,%3}, {%4,%5,%6,%7}, {%8,%9}, {%0,%1,%2,%3};"
        : "+f"(c[0]), "+f"(c[1]), "+f"(c[2]), "+f"(c[3])
        : "r"(a[0]), "r"(a[1]), "r"(a[2]), "r"(a[3]), "r"(b0), "r"(b1));
}

// one launch: zero output + pack W2 fragments + pack W3 fragments
__global__ void prep_zero_kernel(const float* __restrict__ W2,
                                 const float* __restrict__ W3,
                                 float4* __restrict__ out4) {
    int idx = blockIdx.x * 256 + threadIdx.x;
    if (idx < 48000) out4[idx] = make_float4(0.f, 0.f, 0.f, 0.f);

    if (idx < 8192) {               // W2 fragments (validated in R9)
        int lane  = idx & 31;
        int ntile = (idx >> 5) & 15;
        int kk    = (idx >> 9) & 7;
        int spB   = idx >> 12;
        int kp0 = kk * 8 + (lane & 3);
        int n   = ntile * 8 + (lane >> 2);
        float v0 = W2[(2 * kp0) * HH + n];
        float v1 = W2[(2 * kp0 + 1) * HH + n];
        float w0 = W2[(2 * (kp0 + 4)) * HH + n];
        float w1 = W2[(2 * (kp0 + 4) + 1) * HH + n];
        uint32_t b0, b1;
        if (spB == 0) { b0 = bfpack(v0, v1); b1 = bfpack(w0, w1); }
        else {
            b0 = bfpack(v0 - __bfloat162float(__float2bfloat16(v0)),
                        v1 - __bfloat162float(__float2bfloat16(v1)));
            b1 = bfpack(w0 - __bfloat162float(__float2bfloat16(w0)),
                        w1 - __bfloat162float(__float2bfloat16(w1)));
        }
        g_Bfrag[idx] = ((ull)b1 << 32) | (ull)b0;
    } else if (idx < 8192 + 1024) { // W3 fragments, same structure, N=16 (pad)
        int t = idx - 8192;
        int lane = t & 31;
        int nt   = (t >> 5) & 1;
        int kk   = (t >> 6) & 7;
        int spB  = t >> 9;
        int kp0 = kk * 8 + (lane & 3);
        int n   = nt * 8 + (lane >> 2);
        float v0 = 0.f, v1 = 0.f, w0 = 0.f, w1 = 0.f;
        if (n < SS) {
            v0 = W3[(2 * kp0) * SS + n];
            v1 = W3[(2 * kp0 + 1) * SS + n];
            w0 = W3[(2 * (kp0 + 4)) * SS + n];
            w1 = W3[(2 * (kp0 + 4) + 1) * SS + n];
        }
        uint32_t b0, b1;
        if (spB == 0) { b0 = bfpack(v0, v1); b1 = bfpack(w0, w1); }
        else {
            b0 = bfpack(v0 - __bfloat162float(__float2bfloat16(v0)),
                        v1 - __bfloat162float(__float2bfloat16(v1)));
            b1 = bfpack(w0 - __bfloat162float(__float2bfloat16(w0)),
                        w1 - __bfloat162float(__float2bfloat16(w1)));
        }
        g_W3frag[t] = ((ull)b1 << 32) | (ull)b0;
    }
}

__global__ __launch_bounds__(128, 4)
void fused_sensor_kernel(
    const float* __restrict__ de,    // (B,N,3)
    const float* __restrict__ mask,  // (B,N)
    const float* __restrict__ W1,    // (3,H)
    const float* __restrict__ b1,    // (H)
    const float* __restrict__ b2,    // (H)
    const float* __restrict__ b3,    // (S)
    float* __restrict__ out)         // (B,S,T)
{
    extern __shared__ uint32_t smw[];
    float* smf = (float*)smw;
    const uint32_t smb = smem_u32(smw);
    const int tid  = threadIdx.x;
    const int lane = tid & 31;
    const int wid  = tid >> 5;

    // ---- small biases to smem ----
    if (tid < HH) smf[SW_B2 + tid] = b2[tid];
    if (tid < SS) smf[SW_B3 + tid] = b3[tid];

    // ---- layer 1 -> A hi/lo (2 threads/electron, vectorized W1 loads) ----
    const int el = tid >> 1;
    const int q  = tid & 1;
    const int eg = blockIdx.x * EB + el;
    const float x0 = de[3 * eg + 0];
    const float x1 = de[3 * eg + 1];
    const float x2 = de[3 * eg + 2];
    const float msk = mask[eg];
#pragma unroll 4
    for (int i4 = 0; i4 < 16; ++i4) {
        int k = q * 64 + i4 * 4;
        float4 wa = *(const float4*)&W1[k];
        float4 wb = *(const float4*)&W1[HH + k];
        float4 wc = *(const float4*)&W1[2 * HH + k];
        float4 bb = *(const float4*)&b1[k];
        float v0 = fmaxf(fmaf(x2, wc.x, fmaf(x1, wb.x, fmaf(x0, wa.x, bb.x))), 0.f);
        float v1 = fmaxf(fmaf(x2, wc.y, fmaf(x1, wb.y, fmaf(x0, wa.y, bb.y))), 0.f);
        float v2 = fmaxf(fmaf(x2, wc.z, fmaf(x1, wb.z, fmaf(x0, wa.z, bb.z))), 0.f);
        float v3 = fmaxf(fmaf(x2, wc.w, fmaf(x1, wb.w, fmaf(x0, wa.w, bb.w))), 0.f);
        int kp = k >> 1;
        smw[SW_AHI + el * 68 + kp]     = bfpack(v0, v1);
        smw[SW_AHI + el * 68 + kp + 1] = bfpack(v2, v3);
        float h0 = __bfloat162float(__float2bfloat16(v0));
        float h1 = __bfloat162float(__float2bfloat16(v1));
        float h2v = __bfloat162float(__float2bfloat16(v2));
        float h3 = __bfloat162float(__float2bfloat16(v3));
        smw[SW_ALO + el * 68 + kp]     = bfpack(v0 - h0, v1 - h1);
        smw[SW_ALO + el * 68 + kp + 1] = bfpack(v2 - h2v, v3 - h3);
    }
    __syncthreads();

    // ---- layer-2 GEMM: warp (mw,nw) owns 32 rows x 64 cols (R9-validated) ----
    const int mw = wid & 1, nw = wid >> 1;
    const int m0 = mw * 32;
    float acc[2][8][4];
#pragma unroll
    for (int mt = 0; mt < 2; ++mt)
#pragma unroll
        for (int nt = 0; nt < 8; ++nt)
#pragma unroll
            for (int c = 0; c < 4; ++c) acc[mt][nt][c] = 0.0f;

    const uint32_t aoff = ((m0 + (lane & 7) + ((lane >> 3) & 1) * 8) * 68 + (lane >> 4) * 4) * 4;

#pragma unroll 1
    for (int sp = 0; sp < 3; ++sp) {
        const uint32_t Ab = smb + (sp == 1 ? SW_ALO : SW_AHI) * 4 + aoff;
        const ull* Bp = g_Bfrag + (sp == 2 ? 4096 : 0) + nw * 8 * 32 + lane;
#pragma unroll
        for (int kk = 0; kk < 8; ++kk) {
            uint32_t af[2][4];
            ldsm4(af[0], Ab + kk * 32);
            ldsm4(af[1], Ab + 16 * 68 * 4 + kk * 32);
            const ull* Bk = Bp + kk * 512;
            ull bfr[8];
#pragma unroll
            for (int nt = 0; nt < 8; ++nt) bfr[nt] = Bk[nt * 32];
#pragma unroll
            for (int mt = 0; mt < 2; ++mt)
#pragma unroll
                for (int nt = 0; nt < 8; ++nt)
                    mma16816(acc[mt][nt], af[mt],
                             (uint32_t)bfr[nt], (uint32_t)(bfr[nt] >> 32));
        }
    }
    __syncthreads();   // all A reads complete before h2 overwrites the region

    // ---- convert: h2 = relu(D + b2) -> split-bf16 into A region (frag layout) ----
    {
        const int r = lane >> 2, c2 = lane & 3;
#pragma unroll
        for (int mt = 0; mt < 2; ++mt)
#pragma unroll
            for (int nt = 0; nt < 8; ++nt) {
                int j = nw * 64 + nt * 8 + 2 * c2;
                float bj0 = smf[SW_B2 + j], bj1 = smf[SW_B2 + j + 1];
                int row0 = m0 + mt * 16 + r;
                float v0 = fmaxf(acc[mt][nt][0] + bj0, 0.f);
                float v1 = fmaxf(acc[mt][nt][1] + bj1, 0.f);
                float v2 = fmaxf(acc[mt][nt][2] + bj0, 0.f);
                float v3 = fmaxf(acc[mt][nt][3] + bj1, 0.f);
                int w0i = row0 * 68 + (j >> 1);
                int w1i = (row0 + 8) * 68 + (j >> 1);
                smw[SW_AHI + w0i] = bfpack(v0, v1);
                smw[SW_AHI + w1i] = bfpack(v2, v3);
                float p0 = __bfloat162float(__float2bfloat16(v0));
                float p1 = __bfloat162float(__float2bfloat16(v1));
                float p2 = __bfloat162float(__float2bfloat16(v2));
                float p3 = __bfloat162float(__float2bfloat16(v3));
                smw[SW_ALO + w0i] = bfpack(v0 - p0, v1 - p1);
                smw[SW_ALO + w1i] = bfpack(v2 - p2, v3 - p3);
            }
    }
    __syncthreads();

    // ---- layer-3 MMA: M=64 (16 rows/warp), N=16, K=128 ----
    float acc2[2][4];
#pragma unroll
    for (int nt = 0; nt < 2; ++nt)
#pragma unroll
        for (int c = 0; c < 4; ++c) acc2[nt][c] = 0.0f;

    const uint32_t a2off = ((wid * 16 + (lane & 7) + ((lane >> 3) & 1) * 8) * 68 + (lane >> 4) * 4) * 4;
#pragma unroll 1
    for (int sp = 0; sp < 3; ++sp) {
        const uint32_t Ab = smb + (sp == 1 ? SW_ALO : SW_AHI) * 4 + a2off;
        const ull* Wp = g_W3frag + (sp == 2 ? 512 : 0) + lane;
#pragma unroll
        for (int kk = 0; kk < 8; ++kk) {
            uint32_t af[4];
            ldsm4(af, Ab + kk * 32);
            ull f0 = Wp[kk * 64];
            ull f1 = Wp[kk * 64 + 32];
            mma16816(acc2[0], af, (uint32_t)f0, (uint32_t)(f0 >> 32));
            mma16816(acc2[1], af, (uint32_t)f1, (uint32_t)(f1 >> 32));
        }
    }

    // ---- resp to smem: rows = electrons, cols = sensors ----
    {
        const int r = lane >> 2, c2 = lane & 3;
#pragma unroll
        for (int nt = 0; nt < 2; ++nt) {
            int j = nt * 8 + 2 * c2;
            if (j < SS) {
                int row0 = wid * 16 + r;
                *(float2*)&smf[SW_RESP + row0 * SS + j] = make_float2(acc2[nt][0], acc2[nt][1]);
                *(float2*)&smf[SW_RESP + (row0 + 8) * SS + j] = make_float2(acc2[nt][2], acc2[nt][3]);
            }
        }
    }
    __syncthreads();

    // ---- sparse Gaussian scatter (exp(-5d^2) < 3e-20 beyond |d|=3) ----
    {
        float resp[SS];
#pragma unroll
        for (int s = 0; s < SS; ++s)
            resp[s] = smf[SW_RESP + el * SS + s] + smf[SW_B3 + s];

        const float z = x2;
        const float c = msk * MASK_COEF;
        int t0 = (int)ceilf(z - 3.0f);
        int t1 = (int)floorf(z + 3.0f);
        if (t0 < 0) t0 = 0;
        if (t1 > TT - 1) t1 = TT - 1;
        const int b = eg / 10000;
        float* ob = out + (size_t)b * SS * TT;
        for (int t = t0 + q; t <= t1; t += 2) {
            float d = (float)t - z;
            float w = __expf(-5.0f * d * d) * c;
#pragma unroll
            for (int s = 0; s < SS; ++s)
                atomicAdd(&ob[s * TT + t], w * resp[s]);
        }
    }
}

extern "C" void kernel_launch(void* const* d_in, const int* in_sizes, int n_in,
                              void* d_out, int out_size) {
    const float* de   = (const float*)d_in[0];
    const float* mask = (const float*)d_in[1];
    const float* W1   = (const float*)d_in[2];
    const float* b1   = (const float*)d_in[3];
    const float* W2   = (const float*)d_in[4];
    const float* b2   = (const float*)d_in[5];
    const float* W3   = (const float*)d_in[6];
    const float* b3   = (const float*)d_in[7];
    float* out = (float*)d_out;

    // 48000 float4 = 192000 floats zeroed; fragments packed; one launch
    prep_zero_kernel<<<188, 256>>>(W2, W3, (float4*)out);

    const int smem_bytes = SW_TOT * 4;  // 38464
    cudaFuncSetAttribute(fused_sensor_kernel,
                         cudaFuncAttributeMaxDynamicSharedMemorySize, smem_bytes);

    fused_sensor_kernel<<<NE / EB, 128, smem_bytes>>>(   // 1250 CTAs
        de, mask, W1, b1, b2, b3, out);
}